// round 13
// baseline (speedup 1.0000x reference)
#include <cuda_runtime.h>
#include <math.h>
#include <cstdint>

#define GN 50000          // nodes
#define GH 128            // hidden dim
#define EMAX 800000       // edges

// ---------------- device scratch (no allocations allowed) ----------------
__device__ float g_m  [GN * GH];        // message linear output (fp32)
__device__ float g_pre[GN * GH];        // x@Wu^T (bias added in aggregate)
__device__ float g_h  [GN * GH];        // layer activations
__device__ char  g_B8h[3 * 256 * GH];   // [l][j][k] packed Wm|Wu rows, int8 hi
__device__ char  g_B8l[3 * 256 * GH];   // int8 lo
__device__ int   g_rowptr[GN + 1];
__device__ int   g_cursor[GN];
__device__ int   g_src[EMAX];
__device__ float g_wt [EMAX];
__device__ int   g_is64;
__device__ int   g_bitsX;               // absmax(|x|) as float bits
__device__ int   g_bitsW[3];            // absmax(|W|) per layer as float bits

__device__ __forceinline__ uint32_t smem_u32(const void* p) {
    uint32_t a;
    asm("{ .reg .u64 t; cvta.to.shared.u64 t, %1; cvt.u32.u64 %0, t; }"
        : "=r"(a) : "l"(p));
    return a;
}

// ---------------- zero rowptr + init flags ----------------
__global__ void zero_init_kernel() {
    int i = blockIdx.x * blockDim.x + threadIdx.x;
    if (i <= GN) g_rowptr[i] = 0;
    if (i == 0) { g_is64 = 1; g_bitsX = 0; g_bitsW[0] = 0; g_bitsW[1] = 0; g_bitsW[2] = 0; }
}

// ---------------- absmax reductions ----------------
__device__ __forceinline__ void block_amax(float m, int* dst) {
    __shared__ float wmax[8];
    int lane = threadIdx.x & 31;
    int wid  = threadIdx.x >> 5;
    #pragma unroll
    for (int o = 16; o > 0; o >>= 1)
        m = fmaxf(m, __shfl_xor_sync(0xffffffffu, m, o));
    if (lane == 0) wmax[wid] = m;
    __syncthreads();
    if (wid == 0) {
        m = (lane < 8) ? wmax[lane] : 0.f;
        #pragma unroll
        for (int o = 4; o > 0; o >>= 1)
            m = fmaxf(m, __shfl_xor_sync(0xffffffffu, m, o));
        if (lane == 0) atomicMax(dst, __float_as_int(m));
    }
}

__global__ void amax_x_kernel(const float* __restrict__ x) {
    int n = GN * GH;
    float m = 0.f;
    for (int i = blockIdx.x * blockDim.x + threadIdx.x; i < n; i += gridDim.x * blockDim.x)
        m = fmaxf(m, fabsf(x[i]));
    block_amax(m, &g_bitsX);
}

__global__ void amax_w_kernel(
        const float* __restrict__ Wm0, const float* __restrict__ Wu0,
        const float* __restrict__ Wm1, const float* __restrict__ Wu1,
        const float* __restrict__ Wm2, const float* __restrict__ Wu2) {
    int l = blockIdx.y;
    const float* Wm = (l == 0) ? Wm0 : (l == 1) ? Wm1 : Wm2;
    const float* Wu = (l == 0) ? Wu0 : (l == 1) ? Wu1 : Wu2;
    int base = blockIdx.x * 1024;
    float m = 0.f;
    #pragma unroll
    for (int i = 0; i < 4; i++) {
        int rem = base + threadIdx.x + i * 256;   // < 32768
        int j = rem >> 7, k = rem & 127;
        float w = (j < 128) ? Wm[j * GH + k] : Wu[(j - 128) * GH + k];
        m = fmaxf(m, fabsf(w));
    }
    block_amax(m, &g_bitsW[l]);
}

// ---------------- weight quantization to int8 hi/lo ----------------
__device__ __forceinline__ void quant2(float f, int& hi, int& lo) {
    float h = rintf(f);
    float l = rintf((f - h) * 256.f);
    hi = (int)h;
    lo = (int)l;
    if (lo > 127) lo = 127;
    if (lo < -128) lo = -128;
}

__global__ void quant_b_kernel(
        const float* __restrict__ Wm0, const float* __restrict__ Wu0,
        const float* __restrict__ Wm1, const float* __restrict__ Wu1,
        const float* __restrict__ Wm2, const float* __restrict__ Wu2) {
    int idx = blockIdx.x * blockDim.x + threadIdx.x;   // 3*256*128
    if (idx < 3 * 256 * GH) {
        int l   = idx >> 15;
        int rem = idx & 32767;
        int j   = rem >> 7;
        int k   = rem & 127;
        const float* Wm = (l == 0) ? Wm0 : (l == 1) ? Wm1 : Wm2;
        const float* Wu = (l == 0) ? Wu0 : (l == 1) ? Wu1 : Wu2;
        float w = (j < 128) ? Wm[j * GH + k] : Wu[(j - 128) * GH + k];
        float sB = __int_as_float(g_bitsW[l]);
        int hi, lo;
        quant2(w * (127.f / sB), hi, lo);
        g_B8h[idx] = (char)hi;
        g_B8l[idx] = (char)lo;
    }
}

// ---------------- dtype detection + CSR build ----------------
__global__ void detect_kernel(const int* __restrict__ w, int E) {
    int e = blockIdx.x * blockDim.x + threadIdx.x;
    if (e < E) {
        int lo = w[2 * e];
        int hi = w[2 * e + 1];
        if (hi != 0 || lo < 0 || lo >= GN) g_is64 = 0;
    }
}

__global__ void count_kernel(const int* __restrict__ w, int E) {
    int e = blockIdx.x * blockDim.x + threadIdx.x;
    if (e < E) {
        int d = g_is64 ? w[2 * E + 2 * e] : w[E + e];
        if ((unsigned)d < (unsigned)GN) atomicAdd(&g_rowptr[d + 1], 1);
    }
}

__global__ void scan_kernel() {
    __shared__ int wsum[32];
    int tid  = threadIdx.x;
    int lane = tid & 31;
    int wid  = tid >> 5;
    int carry = 0;
    for (int base = 0; base < GN + 1; base += 1024) {
        int i = base + tid;
        int v = (i < GN + 1) ? g_rowptr[i] : 0;
        #pragma unroll
        for (int o = 1; o < 32; o <<= 1) {
            int n = __shfl_up_sync(0xffffffffu, v, o);
            if (lane >= o) v += n;
        }
        if (lane == 31) wsum[wid] = v;
        __syncthreads();
        if (wid == 0) {
            int s = wsum[lane];
            #pragma unroll
            for (int o = 1; o < 32; o <<= 1) {
                int n = __shfl_up_sync(0xffffffffu, s, o);
                if (lane >= o) s += n;
            }
            wsum[lane] = s;
        }
        __syncthreads();
        int add = carry + (wid ? wsum[wid - 1] : 0);
        v += add;
        if (i < GN + 1) g_rowptr[i] = v;
        if (i < GN)     g_cursor[i] = v;
        carry += wsum[31];
        __syncthreads();
    }
}

__global__ void fill_kernel(const int* __restrict__ w,
                            const float* __restrict__ ew, int E) {
    int e = blockIdx.x * blockDim.x + threadIdx.x;
    if (e < E) {
        int s, d;
        if (g_is64) { s = w[2 * e]; d = w[2 * E + 2 * e]; }
        else        { s = w[e];     d = w[E + e]; }
        if ((unsigned)s < (unsigned)GN && (unsigned)d < (unsigned)GN) {
            int p = atomicAdd(&g_cursor[d], 1);
            g_src[p] = s;
            g_wt[p]  = ew[e];
        }
    }
}

// ================= int8 IMMA GEMM =================
// C[128 rows x 256 cols] = A[128x128] @ B[256x128]^T per CTA, s8 2-word split.
// 512 threads = 16 warps (wm 0..3, wn 0..3), warp tile 32 rows x 64 cols.
// Whole K=128 resident (int8): A 16KB hi + 16KB lo, B 32KB hi + 32KB lo = 96KB.
// acc = (Σ AhBh) << 8 + Σ (AhBl + AlBh), exact in s32. cols<128 -> g_m, else g_pre.

#define SM_AH 0
#define SM_AL 16384
#define SM_BH 32768
#define SM_BL 65536
#define SM_TOTAL 98304

__device__ __forceinline__ void ldsm_x4(uint32_t* r, uint32_t addr) {
    asm volatile("ldmatrix.sync.aligned.m8n8.x4.shared.b16 {%0,%1,%2,%3}, [%4];"
                 : "=r"(r[0]), "=r"(r[1]), "=r"(r[2]), "=r"(r[3]) : "r"(addr));
}
__device__ __forceinline__ void ldsm_x2(uint32_t* r, uint32_t addr) {
    asm volatile("ldmatrix.sync.aligned.m8n8.x2.shared.b16 {%0,%1}, [%2];"
                 : "=r"(r[0]), "=r"(r[1]) : "r"(addr));
}
__device__ __forceinline__ void mma_s8(int* d, const uint32_t* a, const uint32_t* b) {
    asm volatile(
        "mma.sync.aligned.m16n8k32.row.col.s32.s8.s8.s32 "
        "{%0,%1,%2,%3}, {%4,%5,%6,%7}, {%8,%9}, {%0,%1,%2,%3};"
        : "+r"(d[0]), "+r"(d[1]), "+r"(d[2]), "+r"(d[3])
        : "r"(a[0]), "r"(a[1]), "r"(a[2]), "r"(a[3]), "r"(b[0]), "r"(b[1]));
}
__device__ __forceinline__ uint32_t pack4(int b0, int b1, int b2, int b3) {
    return (uint32_t)(b0 & 255) | ((uint32_t)(b1 & 255) << 8)
         | ((uint32_t)(b2 & 255) << 16) | ((uint32_t)(b3 & 255) << 24);
}

__global__ void __launch_bounds__(512) gemm_i8_kernel(
        const float* __restrict__ Aext, int use_gh, int layer) {
    extern __shared__ char smem[];
    uint32_t sb = smem_u32(smem);
    const float* A = use_gh ? g_h : Aext;
    int t    = threadIdx.x;
    int lane = t & 31;
    int wid  = t >> 5;
    int wm   = wid & 3;
    int wn   = wid >> 2;
    int row0 = blockIdx.x * 128;

    float sA = (layer == 0) ? __int_as_float(g_bitsX) : 1.0f;
    float sB = __int_as_float(g_bitsW[layer]);
    float qA = 127.f / sA;
    float fin = sA * sB / (127.f * 127.f * 256.f);

    // ---- stage A (128 rows x 128 k int8 hi/lo), swizzled ----
    #pragma unroll
    for (int it = 0; it < 2; it++) {
        int u   = t + it * 512;      // 1024 16B-units
        int r   = u >> 3;
        int seg = u & 7;
        int grow = row0 + r;
        float v[16];
        if (grow < GN) {
            const float4* ap = (const float4*)&A[(size_t)grow * GH + seg * 16];
            float4 a0 = ap[0], a1 = ap[1], a2 = ap[2], a3 = ap[3];
            v[0]=a0.x; v[1]=a0.y; v[2]=a0.z; v[3]=a0.w;
            v[4]=a1.x; v[5]=a1.y; v[6]=a1.z; v[7]=a1.w;
            v[8]=a2.x; v[9]=a2.y; v[10]=a2.z; v[11]=a2.w;
            v[12]=a3.x; v[13]=a3.y; v[14]=a3.z; v[15]=a3.w;
        } else {
            #pragma unroll
            for (int q = 0; q < 16; q++) v[q] = 0.f;
        }
        uint32_t hw[4], lw[4];
        #pragma unroll
        for (int g = 0; g < 4; g++) {
            int h0, l0, h1, l1, h2, l2, h3, l3;
            quant2(v[4*g + 0] * qA, h0, l0);
            quant2(v[4*g + 1] * qA, h1, l1);
            quant2(v[4*g + 2] * qA, h2, l2);
            quant2(v[4*g + 3] * qA, h3, l3);
            hw[g] = pack4(h0, h1, h2, h3);
            lw[g] = pack4(l0, l1, l2, l3);
        }
        uint32_t off = (uint32_t)r * 128 + (uint32_t)((seg ^ (r & 7)) << 4);
        *(uint4*)(smem + SM_AH + off) = make_uint4(hw[0], hw[1], hw[2], hw[3]);
        *(uint4*)(smem + SM_AL + off) = make_uint4(lw[0], lw[1], lw[2], lw[3]);
    }
    // ---- stage B (256 j-rows x 128 k int8), pre-quantized, swizzled ----
    #pragma unroll
    for (int it = 0; it < 4; it++) {
        int u   = t + it * 512;      // 2048 16B-units
        int j   = u >> 3;
        int seg = u & 7;
        size_t src = ((size_t)(layer * 256 + j)) * GH + seg * 16;
        uint4 hv = *(const uint4*)&g_B8h[src];
        uint4 lv = *(const uint4*)&g_B8l[src];
        uint32_t off = (uint32_t)j * 128 + (uint32_t)((seg ^ (j & 7)) << 4);
        *(uint4*)(smem + SM_BH + off) = hv;
        *(uint4*)(smem + SM_BL + off) = lv;
    }
    __syncthreads();

    int acc[2][8][4];
    #pragma unroll
    for (int mi = 0; mi < 2; mi++)
        #pragma unroll
        for (int nj = 0; nj < 8; nj++)
            #pragma unroll
            for (int q = 0; q < 4; q++) acc[mi][nj][q] = 0;

    // ---- phase HI: acc = sum AhBh ----
    #pragma unroll
    for (int ks = 0; ks < 4; ks++) {
        uint32_t ah[2][4];
        #pragma unroll
        for (int mi = 0; mi < 2; mi++) {
            int rr = wm * 32 + mi * 16 + (lane & 7) + ((lane & 8) ? 8 : 0);
            int sg = ks * 2 + ((lane >> 4) & 1);
            uint32_t off = (uint32_t)rr * 128 + (uint32_t)((sg ^ (rr & 7)) << 4);
            ldsm_x4(ah[mi], sb + SM_AH + off);
        }
        #pragma unroll
        for (int nj = 0; nj < 8; nj++) {
            int nn = wn * 64 + nj * 8 + (lane & 7);
            int sg = ks * 2 + ((lane >> 3) & 1);
            uint32_t off = (uint32_t)nn * 128 + (uint32_t)((sg ^ (nn & 7)) << 4);
            uint32_t bh[2];
            ldsm_x2(bh, sb + SM_BH + off);
            #pragma unroll
            for (int mi = 0; mi < 2; mi++) mma_s8(acc[mi][nj], ah[mi], bh);
        }
    }
    // ---- shift: acc <<= 8 (exact; |acc| < 2^31 guaranteed) ----
    #pragma unroll
    for (int mi = 0; mi < 2; mi++)
        #pragma unroll
        for (int nj = 0; nj < 8; nj++)
            #pragma unroll
            for (int q = 0; q < 4; q++) acc[mi][nj][q] <<= 8;

    // ---- phase CROSS: acc += AhBl + AlBh ----
    #pragma unroll
    for (int ks = 0; ks < 4; ks++) {
        uint32_t ah[2][4], al[2][4];
        #pragma unroll
        for (int mi = 0; mi < 2; mi++) {
            int rr = wm * 32 + mi * 16 + (lane & 7) + ((lane & 8) ? 8 : 0);
            int sg = ks * 2 + ((lane >> 4) & 1);
            uint32_t off = (uint32_t)rr * 128 + (uint32_t)((sg ^ (rr & 7)) << 4);
            ldsm_x4(ah[mi], sb + SM_AH + off);
            ldsm_x4(al[mi], sb + SM_AL + off);
        }
        #pragma unroll
        for (int nj = 0; nj < 8; nj++) {
            int nn = wn * 64 + nj * 8 + (lane & 7);
            int sg = ks * 2 + ((lane >> 3) & 1);
            uint32_t off = (uint32_t)nn * 128 + (uint32_t)((sg ^ (nn & 7)) << 4);
            uint32_t bh[2], bl[2];
            ldsm_x2(bh, sb + SM_BH + off);
            ldsm_x2(bl, sb + SM_BL + off);
            #pragma unroll
            for (int mi = 0; mi < 2; mi++) {
                mma_s8(acc[mi][nj], al[mi], bh);
                mma_s8(acc[mi][nj], ah[mi], bl);
            }
        }
    }

    // ---- epilogue: scale to fp32; cols<128 -> g_m, cols>=128 -> g_pre ----
    int gid = lane >> 2;
    int tig = lane & 3;
    #pragma unroll
    for (int mi = 0; mi < 2; mi++) {
        int row = row0 + wm * 32 + mi * 16 + gid;
        #pragma unroll
        for (int nj = 0; nj < 8; nj++) {
            int c  = wn * 64 + nj * 8 + 2 * tig;
            int cc = c & 127;
            float* base = (c < 128) ? g_m : g_pre;
            if (row < GN) {
                float2 v = make_float2((float)acc[mi][nj][0] * fin,
                                       (float)acc[mi][nj][1] * fin);
                *(float2*)&base[(size_t)row * GH + cc] = v;
            }
            if (row + 8 < GN) {
                float2 v = make_float2((float)acc[mi][nj][2] * fin,
                                       (float)acc[mi][nj][3] * fin);
                *(float2*)&base[(size_t)(row + 8) * GH + cc] = v;
            }
        }
    }
}

// ---------------- aggregate + bias + tanh: one warp per destination node -------
__global__ void __launch_bounds__(256) aggregate_kernel(const float* __restrict__ bu) {
    int warp = (blockIdx.x * blockDim.x + threadIdx.x) >> 5;
    int lane = threadIdx.x & 31;
    if (warp >= GN) return;
    int beg = g_rowptr[warp];
    int end = g_rowptr[warp + 1];
    float4 b4   = *(const float4*)&bu[lane * 4];
    float4 pre4 = *(const float4*)&g_pre[(size_t)warp * GH + lane * 4];
    float4 a0 = make_float4(pre4.x + b4.x, pre4.y + b4.y,
                            pre4.z + b4.z, pre4.w + b4.w);
    float4 a1 = make_float4(0.f, 0.f, 0.f, 0.f);
    float4 a2 = a1, a3 = a1;
    int p = beg;
    for (; p + 3 < end; p += 4) {
        int s0 = g_src[p];     float w0 = g_wt[p];
        int s1 = g_src[p + 1]; float w1 = g_wt[p + 1];
        int s2 = g_src[p + 2]; float w2 = g_wt[p + 2];
        int s3 = g_src[p + 3]; float w3 = g_wt[p + 3];
        float4 m0 = *(const float4*)&g_m[(size_t)s0 * GH + lane * 4];
        float4 m1 = *(const float4*)&g_m[(size_t)s1 * GH + lane * 4];
        float4 m2 = *(const float4*)&g_m[(size_t)s2 * GH + lane * 4];
        float4 m3 = *(const float4*)&g_m[(size_t)s3 * GH + lane * 4];
        a0.x = fmaf(w0, m0.x, a0.x); a0.y = fmaf(w0, m0.y, a0.y);
        a0.z = fmaf(w0, m0.z, a0.z); a0.w = fmaf(w0, m0.w, a0.w);
        a1.x = fmaf(w1, m1.x, a1.x); a1.y = fmaf(w1, m1.y, a1.y);
        a1.z = fmaf(w1, m1.z, a1.z); a1.w = fmaf(w1, m1.w, a1.w);
        a2.x = fmaf(w2, m2.x, a2.x); a2.y = fmaf(w2, m2.y, a2.y);
        a2.z = fmaf(w2, m2.z, a2.z); a2.w = fmaf(w2, m2.w, a2.w);
        a3.x = fmaf(w3, m3.x, a3.x); a3.y = fmaf(w3, m3.y, a3.y);
        a3.z = fmaf(w3, m3.z, a3.z); a3.w = fmaf(w3, m3.w, a3.w);
    }
    for (; p < end; p++) {
        int s = g_src[p]; float w = g_wt[p];
        float4 mv = *(const float4*)&g_m[(size_t)s * GH + lane * 4];
        a0.x = fmaf(w, mv.x, a0.x); a0.y = fmaf(w, mv.y, a0.y);
        a0.z = fmaf(w, mv.z, a0.z); a0.w = fmaf(w, mv.w, a0.w);
    }
    a0.x += a1.x + a2.x + a3.x;
    a0.y += a1.y + a2.y + a3.y;
    a0.z += a1.z + a2.z + a3.z;
    a0.w += a1.w + a2.w + a3.w;
    float4 r;
    r.x = tanhf(a0.x); r.y = tanhf(a0.y); r.z = tanhf(a0.z); r.w = tanhf(a0.w);
    *(float4*)&g_h[(size_t)warp * GH + lane * 4] = r;
}

// ---------------- output projection: out = h @ Wout^T + bout ----------------
__global__ void __launch_bounds__(256) out_gemm_kernel(
        const float* __restrict__ Wout, const float* __restrict__ bout,
        float* __restrict__ out) {
    __shared__ float Ws[128][32];
    __shared__ float Hs[8][128];
    int t = threadIdx.x;
    for (int i = t; i < 32 * 128; i += 256) {
        int c = i & 31;
        int k = i >> 5;
        Ws[k][c] = Wout[c * GH + k];
    }
    int row0 = blockIdx.x * 8;
    {
        int idx = t * 4;
        int r   = idx >> 7;
        int k   = idx & 127;
        float4 hv = make_float4(0.f, 0.f, 0.f, 0.f);
        if (row0 + r < GN) hv = *(const float4*)&g_h[(size_t)(row0 + r) * GH + k];
        *(float4*)&Hs[r][k] = hv;
    }
    __syncthreads();
    int w    = t >> 5;
    int lane = t & 31;
    int row  = row0 + w;
    float acc = bout[lane];
    #pragma unroll
    for (int k = 0; k < GH; k++) acc = fmaf(Hs[w][k], Ws[k][lane], acc);
    if (row < GN) out[row * 32 + lane] = acc;
}

// ---------------- launch ----------------
extern "C" void kernel_launch(void* const* d_in, const int* in_sizes, int n_in,
                              void* d_out, int out_size) {
    const float* x    = (const float*)d_in[0];
    const int*   ei   = (const int*)d_in[1];
    const float* ew   = (const float*)d_in[2];
    const float* Wm[3] = {(const float*)d_in[3], (const float*)d_in[6], (const float*)d_in[9]};
    const float* Wu[3] = {(const float*)d_in[4], (const float*)d_in[7], (const float*)d_in[10]};
    const float* bu[3] = {(const float*)d_in[5], (const float*)d_in[8], (const float*)d_in[11]};
    const float* Wout = (const float*)d_in[12];
    const float* bout = (const float*)d_in[13];
    float*       out  = (float*)d_out;

    int E = in_sizes[1] / 2;

    cudaFuncSetAttribute(gemm_i8_kernel,
                         cudaFuncAttributeMaxDynamicSharedMemorySize, SM_TOTAL);

    zero_init_kernel<<<(GN + 256) / 256, 256>>>();
    amax_x_kernel<<<2048, 256>>>(x);
    amax_w_kernel<<<dim3(32, 3), 256>>>(Wm[0], Wu[0], Wm[1], Wu[1], Wm[2], Wu[2]);
    quant_b_kernel<<<(3 * 256 * GH + 255) / 256, 256>>>(
        Wm[0], Wu[0], Wm[1], Wu[1], Wm[2], Wu[2]);

    detect_kernel<<<(E + 255) / 256, 256>>>(ei, E);
    count_kernel<<<(E + 255) / 256, 256>>>(ei, E);
    scan_kernel<<<1, 1024>>>();
    fill_kernel<<<(E + 255) / 256, 256>>>(ei, ew, E);

    int ggrid = (GN + 127) / 128;                 // 391
    int agg_blocks = (GN * 32 + 255) / 256;

    for (int l = 0; l < 3; l++) {
        gemm_i8_kernel<<<ggrid, 512, SM_TOTAL>>>(x, l > 0 ? 1 : 0, l);
        aggregate_kernel<<<agg_blocks, 256>>>(bu[l]);
    }

    out_gemm_kernel<<<(GN + 7) / 8, 256>>>(Wout, bout, out);
}

// round 16
// speedup vs baseline: 1.6265x; 1.6265x over previous
#include <cuda_runtime.h>
#include <cuda_fp16.h>
#include <math.h>
#include <cstdint>

#define GN 50000          // nodes
#define GH 128            // hidden dim
#define EMAX 800000       // edges

// ---------------- device scratch (no allocations allowed) ----------------
__device__ __half g_m [GN * GH];        // message linear output (fp16)
__device__ float g_pre[GN * GH];        // x@Wu^T (bias added in aggregate)
__device__ float g_h  [GN * GH];        // layer activations
__device__ __half g_B16[3 * 256 * GH];  // [l][j][k] packed Wm|Wu rows, fp16
__device__ int   g_rowptr[GN + 1];
__device__ int   g_cursor[GN];
__device__ int   g_src[EMAX];
__device__ float g_wt [EMAX];
__device__ int   g_is64;

__device__ __forceinline__ uint32_t smem_u32(const void* p) {
    uint32_t a;
    asm("{ .reg .u64 t; cvta.to.shared.u64 t, %1; cvt.u32.u64 %0, t; }"
        : "=r"(a) : "l"(p));
    return a;
}

// ---------------- zero rowptr + init detect flag ----------------
__global__ void zero_init_kernel() {
    int i = blockIdx.x * blockDim.x + threadIdx.x;
    if (i <= GN) g_rowptr[i] = 0;
    if (i == 0)  g_is64 = 1;
}

__global__ void detect_kernel(const int* __restrict__ w, int E) {
    int e = blockIdx.x * blockDim.x + threadIdx.x;
    if (e < E) {
        int lo = w[2 * e];
        int hi = w[2 * e + 1];
        if (hi != 0 || lo < 0 || lo >= GN) g_is64 = 0;
    }
}

__global__ void count_kernel(const int* __restrict__ w, int E) {
    int e = blockIdx.x * blockDim.x + threadIdx.x;
    if (e < E) {
        int d = g_is64 ? w[2 * E + 2 * e] : w[E + e];
        if ((unsigned)d < (unsigned)GN) atomicAdd(&g_rowptr[d + 1], 1);
    }
}

__global__ void scan_kernel() {
    __shared__ int wsum[32];
    int tid  = threadIdx.x;
    int lane = tid & 31;
    int wid  = tid >> 5;
    int carry = 0;
    for (int base = 0; base < GN + 1; base += 1024) {
        int i = base + tid;
        int v = (i < GN + 1) ? g_rowptr[i] : 0;
        #pragma unroll
        for (int o = 1; o < 32; o <<= 1) {
            int n = __shfl_up_sync(0xffffffffu, v, o);
            if (lane >= o) v += n;
        }
        if (lane == 31) wsum[wid] = v;
        __syncthreads();
        if (wid == 0) {
            int s = wsum[lane];
            #pragma unroll
            for (int o = 1; o < 32; o <<= 1) {
                int n = __shfl_up_sync(0xffffffffu, s, o);
                if (lane >= o) s += n;
            }
            wsum[lane] = s;
        }
        __syncthreads();
        int add = carry + (wid ? wsum[wid - 1] : 0);
        v += add;
        if (i < GN + 1) g_rowptr[i] = v;
        if (i < GN)     g_cursor[i] = v;
        carry += wsum[31];
        __syncthreads();
    }
}

__global__ void fill_kernel(const int* __restrict__ w,
                            const float* __restrict__ ew, int E) {
    int e = blockIdx.x * blockDim.x + threadIdx.x;
    if (e < E) {
        int s, d;
        if (g_is64) { s = w[2 * e]; d = w[2 * E + 2 * e]; }
        else        { s = w[e];     d = w[E + e]; }
        if ((unsigned)s < (unsigned)GN && (unsigned)d < (unsigned)GN) {
            int p = atomicAdd(&g_cursor[d], 1);
            g_src[p] = s;
            g_wt[p]  = ew[e];
        }
    }
}

// ---------------- weight pack -> fp16, all 3 layers ----------------
// g_B16[l][j][k]: j<128 -> Wm[j][k] (messages), j>=128 -> Wu[j-128][k]
__global__ void pack_b_kernel(
        const float* __restrict__ Wm0, const float* __restrict__ Wu0,
        const float* __restrict__ Wm1, const float* __restrict__ Wu1,
        const float* __restrict__ Wm2, const float* __restrict__ Wu2) {
    int idx = blockIdx.x * blockDim.x + threadIdx.x;   // 3*256*128
    if (idx < 3 * 256 * GH) {
        int l   = idx >> 15;
        int rem = idx & 32767;
        int j   = rem >> 7;
        int k   = rem & 127;
        const float* Wm = (l == 0) ? Wm0 : (l == 1) ? Wm1 : Wm2;
        const float* Wu = (l == 0) ? Wu0 : (l == 1) ? Wu1 : Wu2;
        float w = (j < 128) ? Wm[j * GH + k] : Wu[(j - 128) * GH + k];
        g_B16[idx] = __float2half_rn(w);
    }
}

// ================= fp16 mma.sync GEMM (2-term A split) =================
// C[128 rows x 256 cols] = A[128x128] @ B[256x128]^T per CTA.
// A = Ah + Al (fp16 exact split), B fp16 single. C = Ah*B + Al*B.
// 512 threads = 16 warps (wm 0..3, wn 0..3), warp tile 32 rows x 64 cols.
// Single SMEM stage: A-hi 32KB | A-lo 32KB | B 64KB = 128KB. Rows are 256B
// (16 segs); swizzle: off = r*256 + ((seg ^ (r&15)) << 4)  -> ldmatrix
// conflict-free for any 8-consecutive-row matrix.
// cols<128 -> g_m (fp16), cols>=128 -> g_pre (fp32).

#define SM_AH 0
#define SM_AL 32768
#define SM_B  65536
#define SM_TOTAL 131072

__device__ __forceinline__ void ldsm_x4(uint32_t* r, uint32_t addr) {
    asm volatile("ldmatrix.sync.aligned.m8n8.x4.shared.b16 {%0,%1,%2,%3}, [%4];"
                 : "=r"(r[0]), "=r"(r[1]), "=r"(r[2]), "=r"(r[3]) : "r"(addr));
}
__device__ __forceinline__ void mma_f16(float* d, const uint32_t* a, const uint32_t* b) {
    asm volatile(
        "mma.sync.aligned.m16n8k16.row.col.f32.f16.f16.f32 "
        "{%0,%1,%2,%3}, {%4,%5,%6,%7}, {%8,%9}, {%0,%1,%2,%3};"
        : "+f"(d[0]), "+f"(d[1]), "+f"(d[2]), "+f"(d[3])
        : "r"(a[0]), "r"(a[1]), "r"(a[2]), "r"(a[3]), "r"(b[0]), "r"(b[1]));
}

__global__ void __launch_bounds__(512) gemm_f16_kernel(
        const float* __restrict__ Aext, int use_gh, int layer) {
    extern __shared__ char smem[];
    uint32_t sb = smem_u32(smem);
    const float* A = use_gh ? g_h : Aext;
    int t    = threadIdx.x;
    int lane = t & 31;
    int wid  = t >> 5;
    int wm   = wid & 3;
    int wn   = wid >> 2;
    int row0 = blockIdx.x * 128;

    // ---- stage A (128 rows x 128 k), fp32 -> fp16 hi/lo, swizzled ----
    #pragma unroll
    for (int it = 0; it < 4; it++) {
        int u   = t + it * 512;       // 2048 16B-units
        int r   = u >> 4;
        int seg = u & 15;
        int grow = row0 + r;
        float v[8];
        if (grow < GN) {
            const float4* ap = (const float4*)&A[(size_t)grow * GH + seg * 8];
            float4 v0 = ap[0], v1 = ap[1];
            v[0]=v0.x; v[1]=v0.y; v[2]=v0.z; v[3]=v0.w;
            v[4]=v1.x; v[5]=v1.y; v[6]=v1.z; v[7]=v1.w;
        } else {
            #pragma unroll
            for (int q = 0; q < 8; q++) v[q] = 0.f;
        }
        uint32_t hw[4], lw[4];
        #pragma unroll
        for (int q = 0; q < 4; q++) {
            __half h0 = __float2half_rn(v[2*q]);
            __half h1 = __float2half_rn(v[2*q+1]);
            __half l0 = __float2half_rn(v[2*q]   - __half2float(h0));
            __half l1 = __float2half_rn(v[2*q+1] - __half2float(h1));
            __half2 hh = __halves2half2(h0, h1);
            __half2 ll = __halves2half2(l0, l1);
            hw[q] = *(uint32_t*)&hh;
            lw[q] = *(uint32_t*)&ll;
        }
        uint32_t off = (uint32_t)r * 256 + (uint32_t)((seg ^ (r & 15)) << 4);
        *(uint4*)(smem + SM_AH + off) = make_uint4(hw[0], hw[1], hw[2], hw[3]);
        *(uint4*)(smem + SM_AL + off) = make_uint4(lw[0], lw[1], lw[2], lw[3]);
    }
    // ---- stage B (256 j-rows x 128 k fp16), pre-packed, swizzled ----
    #pragma unroll
    for (int it = 0; it < 8; it++) {
        int u   = t + it * 512;       // 4096 16B-units
        int j   = u >> 4;
        int seg = u & 15;
        uint4 bv = *(const uint4*)&g_B16[((size_t)(layer * 256 + j)) * GH + seg * 8];
        uint32_t off = (uint32_t)j * 256 + (uint32_t)((seg ^ (j & 15)) << 4);
        *(uint4*)(smem + SM_B + off) = bv;
    }
    __syncthreads();

    float acc[2][8][4];
    #pragma unroll
    for (int mi = 0; mi < 2; mi++)
        #pragma unroll
        for (int nj = 0; nj < 8; nj++)
            #pragma unroll
            for (int q = 0; q < 4; q++) acc[mi][nj][q] = 0.f;

    // ---- compute: 8 k16 steps, whole K resident ----
    #pragma unroll
    for (int ks = 0; ks < 8; ks++) {
        uint32_t ah[2][4], al[2][4];
        #pragma unroll
        for (int mi = 0; mi < 2; mi++) {
            int rr = wm * 32 + mi * 16 + (lane & 15);
            int sg = ks * 2 + ((lane >> 4) & 1);
            uint32_t off = (uint32_t)rr * 256 + (uint32_t)((sg ^ (rr & 15)) << 4);
            ldsm_x4(ah[mi], sb + SM_AH + off);
            ldsm_x4(al[mi], sb + SM_AL + off);
        }
        #pragma unroll
        for (int p = 0; p < 4; p++) {
            // x4 B load covers 2 adjacent n8 fragments (nj = 2p, 2p+1)
            int nn = wn * 64 + p * 16 + (lane & 7) + ((lane & 16) ? 8 : 0);
            int sg = ks * 2 + ((lane >> 3) & 1);
            uint32_t off = (uint32_t)nn * 256 + (uint32_t)((sg ^ (nn & 15)) << 4);
            uint32_t bq[4];
            ldsm_x4(bq, sb + SM_B + off);
            #pragma unroll
            for (int mi = 0; mi < 2; mi++) {
                mma_f16(acc[mi][2*p],     ah[mi], bq);
                mma_f16(acc[mi][2*p],     al[mi], bq);
                mma_f16(acc[mi][2*p + 1], ah[mi], bq + 2);
                mma_f16(acc[mi][2*p + 1], al[mi], bq + 2);
            }
        }
    }

    // ---- epilogue: cols<128 -> fp16 g_m, cols>=128 -> fp32 g_pre ----
    int gid = lane >> 2;
    int tig = lane & 3;
    #pragma unroll
    for (int mi = 0; mi < 2; mi++) {
        int row = row0 + wm * 32 + mi * 16 + gid;
        #pragma unroll
        for (int nj = 0; nj < 8; nj++) {
            int c  = wn * 64 + nj * 8 + 2 * tig;
            int cc = c & 127;
            if (c < 128) {
                if (row < GN) {
                    __half2 v = __floats2half2_rn(acc[mi][nj][0], acc[mi][nj][1]);
                    *(__half2*)&g_m[(size_t)row * GH + cc] = v;
                }
                if (row + 8 < GN) {
                    __half2 v = __floats2half2_rn(acc[mi][nj][2], acc[mi][nj][3]);
                    *(__half2*)&g_m[(size_t)(row + 8) * GH + cc] = v;
                }
            } else {
                if (row < GN) {
                    float2 v = make_float2(acc[mi][nj][0], acc[mi][nj][1]);
                    *(float2*)&g_pre[(size_t)row * GH + cc] = v;
                }
                if (row + 8 < GN) {
                    float2 v = make_float2(acc[mi][nj][2], acc[mi][nj][3]);
                    *(float2*)&g_pre[(size_t)(row + 8) * GH + cc] = v;
                }
            }
        }
    }
}

// ---------------- aggregate + bias + tanh: one warp per destination node -------
// gathers fp16 messages (8B/lane/edge), fp32 accumulate
__global__ void __launch_bounds__(256) aggregate_kernel(const float* __restrict__ bu) {
    int warp = (blockIdx.x * blockDim.x + threadIdx.x) >> 5;
    int lane = threadIdx.x & 31;
    if (warp >= GN) return;
    int beg = g_rowptr[warp];
    int end = g_rowptr[warp + 1];
    float4 b4   = *(const float4*)&bu[lane * 4];
    float4 pre4 = *(const float4*)&g_pre[(size_t)warp * GH + lane * 4];
    float4 a0 = make_float4(pre4.x + b4.x, pre4.y + b4.y,
                            pre4.z + b4.z, pre4.w + b4.w);
    float4 a1 = make_float4(0.f, 0.f, 0.f, 0.f);
    float4 a2 = a1, a3 = a1;
    int p = beg;
    for (; p + 3 < end; p += 4) {
        int s0 = g_src[p];     float w0 = g_wt[p];
        int s1 = g_src[p + 1]; float w1 = g_wt[p + 1];
        int s2 = g_src[p + 2]; float w2 = g_wt[p + 2];
        int s3 = g_src[p + 3]; float w3 = g_wt[p + 3];
        uint2 r0 = *(const uint2*)&g_m[(size_t)s0 * GH + lane * 4];
        uint2 r1 = *(const uint2*)&g_m[(size_t)s1 * GH + lane * 4];
        uint2 r2 = *(const uint2*)&g_m[(size_t)s2 * GH + lane * 4];
        uint2 r3 = *(const uint2*)&g_m[(size_t)s3 * GH + lane * 4];
        float2 m0a = __half22float2(*(__half2*)&r0.x), m0b = __half22float2(*(__half2*)&r0.y);
        float2 m1a = __half22float2(*(__half2*)&r1.x), m1b = __half22float2(*(__half2*)&r1.y);
        float2 m2a = __half22float2(*(__half2*)&r2.x), m2b = __half22float2(*(__half2*)&r2.y);
        float2 m3a = __half22float2(*(__half2*)&r3.x), m3b = __half22float2(*(__half2*)&r3.y);
        a0.x = fmaf(w0, m0a.x, a0.x); a0.y = fmaf(w0, m0a.y, a0.y);
        a0.z = fmaf(w0, m0b.x, a0.z); a0.w = fmaf(w0, m0b.y, a0.w);
        a1.x = fmaf(w1, m1a.x, a1.x); a1.y = fmaf(w1, m1a.y, a1.y);
        a1.z = fmaf(w1, m1b.x, a1.z); a1.w = fmaf(w1, m1b.y, a1.w);
        a2.x = fmaf(w2, m2a.x, a2.x); a2.y = fmaf(w2, m2a.y, a2.y);
        a2.z = fmaf(w2, m2b.x, a2.z); a2.w = fmaf(w2, m2b.y, a2.w);
        a3.x = fmaf(w3, m3a.x, a3.x); a3.y = fmaf(w3, m3a.y, a3.y);
        a3.z = fmaf(w3, m3b.x, a3.z); a3.w = fmaf(w3, m3b.y, a3.w);
    }
    for (; p < end; p++) {
        int s = g_src[p]; float w = g_wt[p];
        uint2 r0 = *(const uint2*)&g_m[(size_t)s * GH + lane * 4];
        float2 ma = __half22float2(*(__half2*)&r0.x);
        float2 mb = __half22float2(*(__half2*)&r0.y);
        a0.x = fmaf(w, ma.x, a0.x); a0.y = fmaf(w, ma.y, a0.y);
        a0.z = fmaf(w, mb.x, a0.z); a0.w = fmaf(w, mb.y, a0.w);
    }
    a0.x += a1.x + a2.x + a3.x;
    a0.y += a1.y + a2.y + a3.y;
    a0.z += a1.z + a2.z + a3.z;
    a0.w += a1.w + a2.w + a3.w;
    float4 r;
    r.x = tanhf(a0.x); r.y = tanhf(a0.y); r.z = tanhf(a0.z); r.w = tanhf(a0.w);
    *(float4*)&g_h[(size_t)warp * GH + lane * 4] = r;
}

// ---------------- output projection: out = h @ Wout^T + bout ----------------
__global__ void __launch_bounds__(256) out_gemm_kernel(
        const float* __restrict__ Wout, const float* __restrict__ bout,
        float* __restrict__ out) {
    __shared__ float Ws[128][32];
    __shared__ float Hs[8][128];
    int t = threadIdx.x;
    for (int i = t; i < 32 * 128; i += 256) {
        int c = i & 31;
        int k = i >> 5;
        Ws[k][c] = Wout[c * GH + k];
    }
    int row0 = blockIdx.x * 8;
    {
        int idx = t * 4;
        int r   = idx >> 7;
        int k   = idx & 127;
        float4 hv = make_float4(0.f, 0.f, 0.f, 0.f);
        if (row0 + r < GN) hv = *(const float4*)&g_h[(size_t)(row0 + r) * GH + k];
        *(float4*)&Hs[r][k] = hv;
    }
    __syncthreads();
    int w    = t >> 5;
    int lane = t & 31;
    int row  = row0 + w;
    float acc = bout[lane];
    #pragma unroll
    for (int k = 0; k < GH; k++) acc = fmaf(Hs[w][k], Ws[k][lane], acc);
    if (row < GN) out[row * 32 + lane] = acc;
}

// ---------------- launch ----------------
extern "C" void kernel_launch(void* const* d_in, const int* in_sizes, int n_in,
                              void* d_out, int out_size) {
    const float* x    = (const float*)d_in[0];
    const int*   ei   = (const int*)d_in[1];
    const float* ew   = (const float*)d_in[2];
    const float* Wm[3] = {(const float*)d_in[3], (const float*)d_in[6], (const float*)d_in[9]};
    const float* Wu[3] = {(const float*)d_in[4], (const float*)d_in[7], (const float*)d_in[10]};
    const float* bu[3] = {(const float*)d_in[5], (const float*)d_in[8], (const float*)d_in[11]};
    const float* Wout = (const float*)d_in[12];
    const float* bout = (const float*)d_in[13];
    float*       out  = (float*)d_out;

    int E = in_sizes[1] / 2;

    cudaFuncSetAttribute(gemm_f16_kernel,
                         cudaFuncAttributeMaxDynamicSharedMemorySize, SM_TOTAL);

    pack_b_kernel<<<(3 * 256 * GH + 255) / 256, 256>>>(
        Wm[0], Wu[0], Wm[1], Wu[1], Wm[2], Wu[2]);

    zero_init_kernel<<<(GN + 256) / 256, 256>>>();
    detect_kernel<<<(E + 255) / 256, 256>>>(ei, E);
    count_kernel<<<(E + 255) / 256, 256>>>(ei, E);
    scan_kernel<<<1, 1024>>>();
    fill_kernel<<<(E + 255) / 256, 256>>>(ei, ew, E);

    int ggrid = (GN + 127) / 128;                 // 391
    int agg_blocks = (GN * 32 + 255) / 256;

    for (int l = 0; l < 3; l++) {
        gemm_f16_kernel<<<ggrid, 512, SM_TOTAL>>>(x, l > 0 ? 1 : 0, l);
        aggregate_kernel<<<agg_blocks, 256>>>(bu[l]);
    }

    out_gemm_kernel<<<(GN + 7) / 8, 256>>>(Wout, bout, out);
}